// round 17
// baseline (speedup 1.0000x reference)
#include <cuda_runtime.h>
#include <cuda_fp16.h>
#include <math.h>

#define H_   16
#define DH_  64
#define B_   4
#define N_   2048
#define D_   1024
#define MTOT (B_*N_)     // 8192

__device__ __half g_Qh[(size_t)B_*H_*N_*DH_];   // [b,h,n,d]
__device__ __half g_Kh[(size_t)B_*H_*N_*DH_];
__device__ __half g_Vh[(size_t)B_*H_*N_*DH_];
__device__ __half g_Ah[(size_t)MTOT*D_];        // attention out, [b*n, h*d]
__device__ __half g_Xh[(size_t)MTOT*D_];        // x in fp16
__device__ __half g_Wqh[(size_t)D_*D_];
__device__ __half g_Wkvh[(size_t)D_*2*D_];
__device__ __half g_Woh[(size_t)D_*D_];
__device__ float  g_cos[(size_t)N_*DH_];
__device__ float  g_sin[(size_t)N_*DH_];

// ---------------------------------------------------------------------------
// helpers
// ---------------------------------------------------------------------------
__device__ __forceinline__ unsigned h2u(__half2 h) { return *(unsigned*)&h; }
__device__ __forceinline__ unsigned sptr(const void* p) {
    return (unsigned)__cvta_generic_to_shared(p);
}
__device__ __forceinline__ void mma16(float* c, const unsigned* a, const unsigned* b) {
    asm volatile("mma.sync.aligned.m16n8k16.row.col.f32.f16.f16.f32 "
                 "{%0,%1,%2,%3}, {%4,%5,%6,%7}, {%8,%9}, {%0,%1,%2,%3};"
                 : "+f"(c[0]), "+f"(c[1]), "+f"(c[2]), "+f"(c[3])
                 : "r"(a[0]), "r"(a[1]), "r"(a[2]), "r"(a[3]),
                   "r"(b[0]), "r"(b[1]));
}
__device__ __forceinline__ void ldsm4(unsigned* r, unsigned addr) {
    asm volatile("ldmatrix.sync.aligned.m8n8.x4.shared.b16 {%0,%1,%2,%3}, [%4];"
                 : "=r"(r[0]), "=r"(r[1]), "=r"(r[2]), "=r"(r[3]) : "r"(addr));
}
__device__ __forceinline__ void ldsm4t(unsigned* r, unsigned addr) {
    asm volatile("ldmatrix.sync.aligned.m8n8.x4.trans.shared.b16 {%0,%1,%2,%3}, [%4];"
                 : "=r"(r[0]), "=r"(r[1]), "=r"(r[2]), "=r"(r[3]) : "r"(addr));
}
__device__ __forceinline__ void cpa16(unsigned dst, const void* src) {
    asm volatile("cp.async.cg.shared.global [%0], [%1], 16;" :: "r"(dst), "l"(src));
}
#define CP_COMMIT() asm volatile("cp.async.commit_group;")
#define CP_WAIT0()  asm volatile("cp.async.wait_group 0;")
#define CP_WAIT1()  asm volatile("cp.async.wait_group 1;")

// ---------------------------------------------------------------------------
// f32 -> f16 conversion, unroll-4 for MLP
// ---------------------------------------------------------------------------
__global__ void cvt_h(const float4* __restrict__ src, uint2* __restrict__ dst, int n4)
{
    const int base = blockIdx.x * blockDim.x * 4 + threadIdx.x;
#pragma unroll
    for (int j = 0; j < 4; j++) {
        const int i = base + j * blockDim.x;
        if (i < n4) {
            float4 v = src[i];
            uint2 o;
            o.x = h2u(__floats2half2_rn(v.x, v.y));
            o.y = h2u(__floats2half2_rn(v.z, v.w));
            dst[i] = o;
        }
    }
}

// ---------------------------------------------------------------------------
// Precompute cos/sin tables of rot
// ---------------------------------------------------------------------------
__global__ void prep_trig(const float* __restrict__ rot)
{
    const int i = blockIdx.x * blockDim.x + threadIdx.x;
    if (i < N_*DH_) {
        g_cos[i] = cosf(rot[i]);
        g_sin[i] = sinf(rot[i]);
    }
}

// ---------------------------------------------------------------------------
// GEMM plumbing: 128x256 block, 8 warps (2m x 4n), warp tile 64x64, BK=32,
// 2-stage cp.async double buffer.
// ---------------------------------------------------------------------------
#define AST 40                        // 32 + 8 pad (halves)
#define BST 264                       // 256 + 8 pad (halves)
#define ABUF (128*AST)                // halves per A stage (5120)
#define BBUF (32*BST)                 // halves per B stage (8448)
#define GEMM_BYTES ((2*ABUF + 2*BBUF)*2)   // 54272

// ---------------------------------------------------------------------------
// Fused QKV projection GEMM: N' = 3072 (Q | K | V), rope+scale in epilogue.
// grid (12, 64)
// ---------------------------------------------------------------------------
__global__ __launch_bounds__(256)
void gemm_qkv(const __half* __restrict__ A,
              const __half* __restrict__ Wq, const __half* __restrict__ Wkv)
{
    extern __shared__ __half dsm[];
    __half* As = dsm;
    __half* Bs = dsm + 2*ABUF;
    const int tid  = threadIdx.x;
    const int lane = tid & 31;
    const int wid  = tid >> 5;
    const int wm   = wid & 1;          // 2 warps in m, 64 rows each
    const int wn   = wid >> 1;         // 4 warps in n, 64 cols each
    const int m0 = blockIdx.y * 128, n0 = blockIdx.x * 256;
    const int K = D_;

    // B source for this block's 256 columns (never straddles Q|KV boundary)
    const __half* Bp; int ldb;
    if (n0 < 1024) { Bp = Wq  + n0;          ldb = 1024; }
    else           { Bp = Wkv + (n0 - 1024); ldb = 2048; }

    const unsigned asU = sptr(As);
    const unsigned bsU = sptr(Bs);

    float acc[4][8][4];
#pragma unroll
    for (int i = 0; i < 4; i++)
#pragma unroll
        for (int j = 0; j < 8; j++)
#pragma unroll
            for (int v = 0; v < 4; v++) acc[i][j][v] = 0.f;

    unsigned aAd[4], bAd[4];
#pragma unroll
    for (int mt = 0; mt < 4; mt++)
        aAd[mt] = asU + ((wm*64 + mt*16 + (lane & 15))*AST + (lane >> 4)*8) * 2;
#pragma unroll
    for (int p = 0; p < 4; p++)
        bAd[p] = bsU + ((lane & 15)*BST + wn*64 + p*16 + (lane >> 4)*8) * 2;

    auto issue = [&](int k0, int s) {
        const unsigned ad = asU + s * (ABUF*2);
        const unsigned bd = bsU + s * (BBUF*2);
#pragma unroll
        for (int it = 0; it < 2; it++) {       // A: 512 chunks
            const int ch = tid*2 + it;
            const int row = ch >> 2, c = (ch & 3)*8;
            cpa16(ad + (row*AST + c)*2, A + (size_t)(m0+row)*K + k0 + c);
        }
#pragma unroll
        for (int it = 0; it < 4; it++) {       // B: 1024 chunks
            const int ch2 = tid + it*256;
            const int br = ch2 >> 5, bc = (ch2 & 31)*8;
            cpa16(bd + (br*BST + bc)*2, Bp + (size_t)(k0+br)*ldb + bc);
        }
        CP_COMMIT();
    };

    issue(0, 0);

    for (int k0 = 0; k0 < K; k0 += 32) {
        const int buf = (k0 >> 5) & 1;
        CP_WAIT0();
        __syncthreads();
        if (k0 + 32 < K) issue(k0 + 32, buf ^ 1);

        const unsigned aOff = buf * (ABUF*2);
        const unsigned bOff = buf * (BBUF*2);
#pragma unroll
        for (int ks = 0; ks < 2; ks++) {
            unsigned af[4][4];
#pragma unroll
            for (int mt = 0; mt < 4; mt++)
                ldsm4(af[mt], aAd[mt] + aOff + ks*32);
#pragma unroll
            for (int p = 0; p < 4; p++) {
                unsigned bb[4];
                ldsm4t(bb, bAd[p] + bOff + ks*(16*BST*2));
#pragma unroll
                for (int mt = 0; mt < 4; mt++) {
                    mma16(acc[mt][2*p+0], af[mt], &bb[0]);
                    mma16(acc[mt][2*p+1], af[mt], &bb[2]);
                }
            }
        }
    }

    // --- epilogue with fused rope (+ QSC on Q) ---
    const float QSC = 0.125f * 1.4426950408889634f;
    const int cbase = n0 + wn*64;          // one head-wide group
    const int region = cbase >> 10;        // 0=Q, 1=K, 2=V
    const int h = (cbase >> 6) & 15;
    __half* dst = (region == 0) ? g_Qh : (region == 1) ? g_Kh : g_Vh;

#pragma unroll
    for (int mt = 0; mt < 4; mt++) {
        const int r0 = m0 + wm*64 + mt*16 + (lane >> 2);
#pragma unroll
        for (int half = 0; half < 2; half++) {
            const int row = r0 + half*8;
            const int b = row >> 11, n = row & 2047;
            __half* rowp = dst + ((size_t)(b*H_ + h)*N_ + n)*DH_;
#pragma unroll
            for (int nt = 0; nt < 4; nt++) {
                const int d = nt*8 + (lane & 3)*2;      // d < 32
                float x1 = acc[mt][nt  ][half*2+0];
                float y1 = acc[mt][nt  ][half*2+1];
                float x2 = acc[mt][nt+4][half*2+0];
                float y2 = acc[mt][nt+4][half*2+1];
                if (region < 2) {
                    const float2 c1 = *(const float2*)&g_cos[n*64 + d];
                    const float2 s1 = *(const float2*)&g_sin[n*64 + d];
                    const float2 c2 = *(const float2*)&g_cos[n*64 + d + 32];
                    const float2 s2 = *(const float2*)&g_sin[n*64 + d + 32];
                    float o1x = x1*c1.x - x2*s1.x;
                    float o1y = y1*c1.y - y2*s1.y;
                    float o2x = x2*c2.x + x1*s2.x;
                    float o2y = y2*c2.y + y1*s2.y;
                    if (region == 0) {
                        o1x *= QSC; o1y *= QSC; o2x *= QSC; o2y *= QSC;
                    }
                    x1 = o1x; y1 = o1y; x2 = o2x; y2 = o2y;
                }
                *(__half2*)&rowp[d]      = __floats2half2_rn(x1, y1);
                *(__half2*)&rowp[d + 32] = __floats2half2_rn(x2, y2);
            }
        }
    }
}

// ---------------------------------------------------------------------------
// Output GEMM: out = g_Ah @ Woh + bias (fp32 out). grid (4, 64)
// ---------------------------------------------------------------------------
__global__ __launch_bounds__(256)
void gemm_out(const __half* __restrict__ A, const __half* __restrict__ Bm,
              float* __restrict__ C, const float* __restrict__ bias)
{
    extern __shared__ __half dsm[];
    __half* As = dsm;
    __half* Bs = dsm + 2*ABUF;
    const int tid  = threadIdx.x;
    const int lane = tid & 31;
    const int wid  = tid >> 5;
    const int wm   = wid & 1;
    const int wn   = wid >> 1;
    const int m0 = blockIdx.y * 128, n0 = blockIdx.x * 256;
    const int K = D_, N = D_;

    const unsigned asU = sptr(As);
    const unsigned bsU = sptr(Bs);

    float acc[4][8][4];
#pragma unroll
    for (int i = 0; i < 4; i++)
#pragma unroll
        for (int j = 0; j < 8; j++)
#pragma unroll
            for (int v = 0; v < 4; v++) acc[i][j][v] = 0.f;

    unsigned aAd[4], bAd[4];
#pragma unroll
    for (int mt = 0; mt < 4; mt++)
        aAd[mt] = asU + ((wm*64 + mt*16 + (lane & 15))*AST + (lane >> 4)*8) * 2;
#pragma unroll
    for (int p = 0; p < 4; p++)
        bAd[p] = bsU + ((lane & 15)*BST + wn*64 + p*16 + (lane >> 4)*8) * 2;

    auto issue = [&](int k0, int s) {
        const unsigned ad = asU + s * (ABUF*2);
        const unsigned bd = bsU + s * (BBUF*2);
#pragma unroll
        for (int it = 0; it < 2; it++) {
            const int ch = tid*2 + it;
            const int row = ch >> 2, c = (ch & 3)*8;
            cpa16(ad + (row*AST + c)*2, A + (size_t)(m0+row)*K + k0 + c);
        }
#pragma unroll
        for (int it = 0; it < 4; it++) {
            const int ch2 = tid + it*256;
            const int br = ch2 >> 5, bc = (ch2 & 31)*8;
            cpa16(bd + (br*BST + bc)*2, Bm + (size_t)(k0+br)*N + n0 + bc);
        }
        CP_COMMIT();
    };

    issue(0, 0);

    for (int k0 = 0; k0 < K; k0 += 32) {
        const int buf = (k0 >> 5) & 1;
        CP_WAIT0();
        __syncthreads();
        if (k0 + 32 < K) issue(k0 + 32, buf ^ 1);

        const unsigned aOff = buf * (ABUF*2);
        const unsigned bOff = buf * (BBUF*2);
#pragma unroll
        for (int ks = 0; ks < 2; ks++) {
            unsigned af[4][4];
#pragma unroll
            for (int mt = 0; mt < 4; mt++)
                ldsm4(af[mt], aAd[mt] + aOff + ks*32);
#pragma unroll
            for (int p = 0; p < 4; p++) {
                unsigned bb[4];
                ldsm4t(bb, bAd[p] + bOff + ks*(16*BST*2));
#pragma unroll
                for (int mt = 0; mt < 4; mt++) {
                    mma16(acc[mt][2*p+0], af[mt], &bb[0]);
                    mma16(acc[mt][2*p+1], af[mt], &bb[2]);
                }
            }
        }
    }

#pragma unroll
    for (int mt = 0; mt < 4; mt++) {
        const int r0 = m0 + wm*64 + mt*16 + (lane >> 2);
#pragma unroll
        for (int nt = 0; nt < 8; nt++) {
            const int c = n0 + wn*64 + nt*8 + (lane & 3)*2;
#pragma unroll
            for (int half = 0; half < 2; half++) {
                const int row = r0 + half*8;
                float2 v;
                v.x = acc[mt][nt][half*2+0] + bias[c];
                v.y = acc[mt][nt][half*2+1] + bias[c+1];
                *(float2*)&C[(size_t)row*N + c] = v;
            }
        }
    }
}

// ---------------------------------------------------------------------------
// Flash attention (fp16 mma, register-resident P): 128-row blocks, 4 warps,
// 32 q-rows/warp, 3-stage cp.async K/V ring, exp2 softmax, alpha-skip.
// (unchanged from the 519.6us-passing version)
// ---------------------------------------------------------------------------
#define KST 72
#define VST 72
#define KS_FL (64*KST)
#define VS_FL (64*VST)
#define ATT_BYTES ((3*KS_FL + 3*VS_FL)*2)     // 55296
#define NT_ (N_/64)

__global__ __launch_bounds__(128)
void attn_mma()
{
    extern __shared__ __half smh[];
    __half* KsB = smh;
    __half* VsB = smh + 3*KS_FL;

    const int tid  = threadIdx.x;
    const int lane = tid & 31;
    const int wid  = tid >> 5;
    const int bh = blockIdx.y;
    const int m0 = blockIdx.x * 128;

    const unsigned ksU = sptr(KsB);
    const unsigned vsU = sptr(VsB);

    const __half* Qb = g_Qh + (size_t)bh * N_ * DH_;
    const int qr = m0 + wid*32 + (lane >> 2);
    unsigned qf[2][4][4];
#pragma unroll
    for (int mt = 0; mt < 2; mt++) {
#pragma unroll
        for (int ks = 0; ks < 4; ks++) {
#pragma unroll
            for (int v = 0; v < 4; v++) {
                const int rr = qr + mt*16 + (v & 1)*8;
                const int cc = ks*16 + (lane & 3)*2 + (v >> 1)*8;
                qf[mt][ks][v] = *(const unsigned*)&Qb[(size_t)rr*64 + cc];
            }
        }
    }

    unsigned kAd[4], vAd[4];
#pragma unroll
    for (int p = 0; p < 4; p++)
        kAd[p] = ksU + ((p*16 + (lane & 7) + (lane >> 4)*8)*KST
                        + ((lane >> 3) & 1)*8) * 2;
#pragma unroll
    for (int dv = 0; dv < 4; dv++)
        vAd[dv] = vsU + ((lane & 15)*VST + dv*16 + (lane >> 4)*8) * 2;

    float mi[4] = {-1e30f, -1e30f, -1e30f, -1e30f};
    float li[4] = {0.f, 0.f, 0.f, 0.f};
    float o[2][8][4];
#pragma unroll
    for (int mt = 0; mt < 2; mt++)
#pragma unroll
        for (int nt = 0; nt < 8; nt++)
#pragma unroll
            for (int v = 0; v < 4; v++) o[mt][nt][v] = 0.f;

    const __half* KgB = g_Kh + (size_t)bh * N_ * DH_;
    const __half* VgB = g_Vh + (size_t)bh * N_ * DH_;

    auto issue = [&](int jt, int s) {
        const __half* Kg = KgB + (size_t)jt * 64 * 64;
        const __half* Vg = VgB + (size_t)jt * 64 * 64;
        const unsigned kd = ksU + s * (KS_FL*2);
        const unsigned vd = vsU + s * (VS_FL*2);
#pragma unroll
        for (int it = 0; it < 4; it++) {
            const int t = tid + it*128;
            const int row = t >> 3, c8 = (t & 7) * 8;
            cpa16(kd + (row*KST + c8)*2, Kg + row*64 + c8);
            cpa16(vd + (row*VST + c8)*2, Vg + row*64 + c8);
        }
        CP_COMMIT();
    };

    issue(0, 0);
    issue(1, 1);

    for (int jt = 0; jt < NT_; jt++) {
        const int st = jt % 3;
        if (jt + 1 < NT_) { CP_WAIT1(); } else { CP_WAIT0(); }
        __syncthreads();
        if (jt + 2 < NT_) issue(jt + 2, (jt + 2) % 3);

        const unsigned kOff = st * (KS_FL*2);
        float s[2][8][4];
#pragma unroll
        for (int mt = 0; mt < 2; mt++)
#pragma unroll
            for (int nt = 0; nt < 8; nt++)
#pragma unroll
                for (int v = 0; v < 4; v++) s[mt][nt][v] = 0.f;
#pragma unroll
        for (int ks = 0; ks < 4; ks++) {
#pragma unroll
            for (int p = 0; p < 4; p++) {
                unsigned bb[4];
                ldsm4(bb, kAd[p] + kOff + ks*32);
                mma16(s[0][2*p+0], qf[0][ks], &bb[0]);
                mma16(s[0][2*p+1], qf[0][ks], &bb[2]);
                mma16(s[1][2*p+0], qf[1][ks], &bb[0]);
                mma16(s[1][2*p+1], qf[1][ks], &bb[2]);
            }
        }

        unsigned ph[2][4][4];
#pragma unroll
        for (int mt = 0; mt < 2; mt++) {
            float mx0 = -1e30f, mx1 = -1e30f;
#pragma unroll
            for (int nt = 0; nt < 8; nt++) {
                mx0 = fmaxf(mx0, fmaxf(s[mt][nt][0], s[mt][nt][1]));
                mx1 = fmaxf(mx1, fmaxf(s[mt][nt][2], s[mt][nt][3]));
            }
#pragma unroll
            for (int off = 1; off <= 2; off <<= 1) {
                mx0 = fmaxf(mx0, __shfl_xor_sync(0xffffffffu, mx0, off));
                mx1 = fmaxf(mx1, __shfl_xor_sync(0xffffffffu, mx1, off));
            }
            const float mn0 = fmaxf(mi[mt*2+0], mx0);
            const float mn1 = fmaxf(mi[mt*2+1], mx1);
            const float al0 = exp2f(mi[mt*2+0] - mn0);
            const float al1 = exp2f(mi[mt*2+1] - mn1);
            float rs0 = 0.f, rs1 = 0.f;
#pragma unroll
            for (int nt = 0; nt < 8; nt++) {
                float p0 = exp2f(s[mt][nt][0] - mn0);
                float p1 = exp2f(s[mt][nt][1] - mn0);
                float p2 = exp2f(s[mt][nt][2] - mn1);
                float p3 = exp2f(s[mt][nt][3] - mn1);
                rs0 += p0 + p1; rs1 += p2 + p3;
                const int ks = nt >> 1, hi = (nt & 1) * 2;
                ph[mt][ks][hi+0] = h2u(__floats2half2_rn(p0, p1));
                ph[mt][ks][hi+1] = h2u(__floats2half2_rn(p2, p3));
            }
#pragma unroll
            for (int off = 1; off <= 2; off <<= 1) {
                rs0 += __shfl_xor_sync(0xffffffffu, rs0, off);
                rs1 += __shfl_xor_sync(0xffffffffu, rs1, off);
            }
            li[mt*2+0] = li[mt*2+0]*al0 + rs0;  mi[mt*2+0] = mn0;
            li[mt*2+1] = li[mt*2+1]*al1 + rs1;  mi[mt*2+1] = mn1;
            const bool skip = __all_sync(0xffffffffu,
                                         (al0 == 1.f) && (al1 == 1.f));
            if (!skip) {
#pragma unroll
                for (int nt = 0; nt < 8; nt++) {
                    o[mt][nt][0] *= al0; o[mt][nt][1] *= al0;
                    o[mt][nt][2] *= al1; o[mt][nt][3] *= al1;
                }
            }
        }

        const unsigned vOff = st * (VS_FL*2);
#pragma unroll
        for (int ks = 0; ks < 4; ks++) {
#pragma unroll
            for (int dv = 0; dv < 4; dv++) {
                unsigned bb[4];
                ldsm4t(bb, vAd[dv] + vOff + ks*(16*VST*2));
                mma16(o[0][2*dv+0], ph[0][ks], &bb[0]);
                mma16(o[0][2*dv+1], ph[0][ks], &bb[2]);
                mma16(o[1][2*dv+0], ph[1][ks], &bb[0]);
                mma16(o[1][2*dv+1], ph[1][ks], &bb[2]);
            }
        }
    }

    const int b = bh >> 4, h = bh & 15;
#pragma unroll
    for (int mt = 0; mt < 2; mt++) {
        const float inv0 = 1.f / li[mt*2+0];
        const float inv1 = 1.f / li[mt*2+1];
        const int r0 = m0 + wid*32 + mt*16 + (lane >> 2);
#pragma unroll
        for (int nt = 0; nt < 8; nt++) {
            const int c = h*64 + nt*8 + (lane & 3)*2;
            *(__half2*)&g_Ah[((size_t)(b*N_ + r0))*D_ + c] =
                __floats2half2_rn(o[mt][nt][0]*inv0, o[mt][nt][1]*inv0);
            *(__half2*)&g_Ah[((size_t)(b*N_ + r0 + 8))*D_ + c] =
                __floats2half2_rn(o[mt][nt][2]*inv1, o[mt][nt][3]*inv1);
        }
    }
}

// ---------------------------------------------------------------------------
extern "C" void kernel_launch(void* const* d_in, const int* in_sizes, int n_in,
                              void* d_out, int out_size)
{
    const float* x    = (const float*)d_in[0];
    const float* rot  = (const float*)d_in[1];
    const float* Wq   = (const float*)d_in[2];
    const float* Wkv  = (const float*)d_in[3];
    const float* Wout = (const float*)d_in[4];
    const float* bout = (const float*)d_in[5];
    float* out = (float*)d_out;

    __half *gXh, *gWqh, *gWkvh, *gWoh, *gAh;
    cudaGetSymbolAddress((void**)&gXh,  g_Xh);
    cudaGetSymbolAddress((void**)&gWqh, g_Wqh);
    cudaGetSymbolAddress((void**)&gWkvh,g_Wkvh);
    cudaGetSymbolAddress((void**)&gWoh, g_Woh);
    cudaGetSymbolAddress((void**)&gAh,  g_Ah);

    cudaFuncSetAttribute(attn_mma,
                         cudaFuncAttributeMaxDynamicSharedMemorySize, ATT_BYTES);
    cudaFuncSetAttribute(gemm_qkv,
                         cudaFuncAttributeMaxDynamicSharedMemorySize, GEMM_BYTES);
    cudaFuncSetAttribute(gemm_out,
                         cudaFuncAttributeMaxDynamicSharedMemorySize, GEMM_BYTES);

    prep_trig<<<(N_*DH_ + 255)/256, 256>>>(rot);
    cvt_h<<<MTOT*D_/4/1024, 256>>>((const float4*)x,    (uint2*)gXh,   MTOT*D_/4);
    cvt_h<<<D_*D_/4/1024,   256>>>((const float4*)Wq,   (uint2*)gWqh,  D_*D_/4);
    cvt_h<<<D_*2*D_/4/1024, 256>>>((const float4*)Wkv,  (uint2*)gWkvh, D_*2*D_/4);
    cvt_h<<<D_*D_/4/1024,   256>>>((const float4*)Wout, (uint2*)gWoh,  D_*D_/4);

    gemm_qkv<<<dim3(12, 64), 256, GEMM_BYTES>>>(gXh, gWqh, gWkvh);
    attn_mma<<<dim3(N_/128, B_*H_), 128, ATT_BYTES>>>();
    gemm_out<<<dim3(4, 64), 256, GEMM_BYTES>>>(gAh, gWoh, out, bout);
}